// round 1
// baseline (speedup 1.0000x reference)
#include <cuda_runtime.h>
#include <cstdint>

// Problem constants (capacities; actual sizes taken from in_sizes at runtime)
#define MAXN 50048
#define F    128   // in = out feats
#define F4   32    // float4s per row

// Scratch (device globals: no allocation allowed)
__device__ float g_h[(size_t)MAXN * F];   // aggregated features
__device__ int   g_dout[MAXN];
__device__ int   g_din[MAXN];
__device__ float g_iso[MAXN];             // deg_out^{-1/2}
__device__ float g_isi[MAXN];             // deg_in^{-1/2}

// ---------------------------------------------------------------------------
// K0: zero h and degree counters
// ---------------------------------------------------------------------------
__global__ void k_init(int n) {
    int i = blockIdx.x * blockDim.x + threadIdx.x;
    int stride = gridDim.x * blockDim.x;
    float4 z = make_float4(0.f, 0.f, 0.f, 0.f);
    float4* h4 = reinterpret_cast<float4*>(g_h);
    int total = n * F4;
    for (int t = i; t < total; t += stride) h4[t] = z;
    for (int t = i; t < n; t += stride) { g_dout[t] = 0; g_din[t] = 0; }
}

// ---------------------------------------------------------------------------
// K1: degree histograms
// ---------------------------------------------------------------------------
__global__ void k_deg(const int* __restrict__ src, const int* __restrict__ dst, int E) {
    int i = blockIdx.x * blockDim.x + threadIdx.x;
    int stride = gridDim.x * blockDim.x;
    for (int e = i; e < E; e += stride) {
        atomicAdd(&g_dout[src[e]], 1);
        atomicAdd(&g_din[dst[e]], 1);
    }
}

// ---------------------------------------------------------------------------
// K2: inverse-sqrt degree (clamped to >= 1)
// ---------------------------------------------------------------------------
__global__ void k_inv(int n) {
    int i = blockIdx.x * blockDim.x + threadIdx.x;
    int stride = gridDim.x * blockDim.x;
    for (int t = i; t < n; t += stride) {
        int dOut = g_dout[t]; if (dOut < 1) dOut = 1;
        int dIn  = g_din[t];  if (dIn  < 1) dIn  = 1;
        g_iso[t] = rsqrtf((float)dOut);
        g_isi[t] = rsqrtf((float)dIn);
    }
}

// ---------------------------------------------------------------------------
// K3: edge scatter  h[dst] += x[src] * iso[src]
// One warp per edge; lane l handles float4 chunk l of the 128-float row.
// Vector reduction (red.global.add.v4.f32, sm_90+) — no return value, pipelines
// at the LTS. x and h both fit in L2, so this is L2-bound.
// ---------------------------------------------------------------------------
__global__ void k_scatter(const float* __restrict__ x,
                          const int* __restrict__ src,
                          const int* __restrict__ dst, int E) {
    int gtid = blockIdx.x * blockDim.x + threadIdx.x;
    int warp = gtid >> 5;
    int lane = gtid & 31;
    int nwarps = (gridDim.x * blockDim.x) >> 5;
    const float4* x4 = reinterpret_cast<const float4*>(x);
    float4* h4 = reinterpret_cast<float4*>(g_h);
    for (int e = warp; e < E; e += nwarps) {
        int s = src[e];
        int d = dst[e];
        float sc = g_iso[s];
        float4 v = x4[(size_t)s * F4 + lane];
        v.x *= sc; v.y *= sc; v.z *= sc; v.w *= sc;
        float4* p = &h4[(size_t)d * F4 + lane];
        asm volatile("red.global.add.v4.f32 [%0], {%1,%2,%3,%4};"
                     :: "l"(p), "f"(v.x), "f"(v.y), "f"(v.z), "f"(v.w)
                     : "memory");
    }
}

// ---------------------------------------------------------------------------
// K4: out = (h @ W) * isi[row] + bias
// Tile: 64 rows x 128 cols per block, K-tiles of 32. 256 threads:
// 32 thread-cols (4 cols each, float4) x 8 thread-rows (8 rows each).
// Inner product uses packed fma.rn.f32x2 (2 FMAs/instr on Blackwell fma pipe).
// ---------------------------------------------------------------------------
__global__ void k_gemm(const float* __restrict__ W,
                       const float* __restrict__ bias,
                       float* __restrict__ out, int n) {
    __shared__ float Ws[32][F];     // [kk][col]   16 KB
    __shared__ float Hs[64][32];    // [row][kk]    8 KB

    int tid  = threadIdx.x;          // 0..255
    int tcol = tid & 31;             // col4 index: cols 4*tcol .. 4*tcol+3
    int trow = tid >> 5;             // 0..7 -> rows trow*8 .. trow*8+7
    int row0 = blockIdx.x * 64;

    unsigned long long acc2[8][2];   // 8 rows x 4 cols as 2x f32x2 each
    #pragma unroll
    for (int r = 0; r < 8; r++) { acc2[r][0] = 0ull; acc2[r][1] = 0ull; }

    const float4* h4 = reinterpret_cast<const float4*>(g_h);

    for (int kt = 0; kt < 4; kt++) {
        int k0 = kt * 32;
        // load W tile: 32x128 floats = 1024 float4, 4 per thread
        #pragma unroll
        for (int i = tid; i < 1024; i += 256) {
            int wr = i >> 5;         // 0..31
            int wc = i & 31;         // float4 col
            float4 wv = reinterpret_cast<const float4*>(W)[(size_t)(k0 + wr) * F4 + wc];
            *reinterpret_cast<float4*>(&Ws[wr][wc << 2]) = wv;
        }
        // load H tile: 64x32 floats = 512 float4, 2 per thread
        #pragma unroll
        for (int i = tid; i < 512; i += 256) {
            int hr = i >> 3;         // 0..63
            int hc = i & 7;          // float4 within the 32-col k-tile
            int gr = row0 + hr;
            float4 hv = make_float4(0.f, 0.f, 0.f, 0.f);
            if (gr < n) hv = h4[(size_t)gr * F4 + (k0 >> 2) + hc];
            *reinterpret_cast<float4*>(&Hs[hr][hc << 2]) = hv;
        }
        __syncthreads();

        #pragma unroll
        for (int kk = 0; kk < 32; kk++) {
            float4 wv = *reinterpret_cast<const float4*>(&Ws[kk][tcol << 2]);
            unsigned long long wlo, whi;
            asm("mov.b64 %0, {%1,%2};" : "=l"(wlo) : "f"(wv.x), "f"(wv.y));
            asm("mov.b64 %0, {%1,%2};" : "=l"(whi) : "f"(wv.z), "f"(wv.w));
            #pragma unroll
            for (int r = 0; r < 8; r++) {
                float hv = Hs[trow * 8 + r][kk];
                unsigned long long hh;
                asm("mov.b64 %0, {%1,%1};" : "=l"(hh) : "f"(hv));
                asm("fma.rn.f32x2 %0, %1, %2, %0;"
                    : "+l"(acc2[r][0]) : "l"(hh), "l"(wlo));
                asm("fma.rn.f32x2 %0, %1, %2, %0;"
                    : "+l"(acc2[r][1]) : "l"(hh), "l"(whi));
            }
        }
        __syncthreads();
    }

    float4 bv = reinterpret_cast<const float4*>(bias)[tcol];
    #pragma unroll
    for (int r = 0; r < 8; r++) {
        int row = row0 + trow * 8 + r;
        if (row < n) {
            float s = g_isi[row];
            float ax, ay, az, aw;
            asm("mov.b64 {%0,%1}, %2;" : "=f"(ax), "=f"(ay) : "l"(acc2[r][0]));
            asm("mov.b64 {%0,%1}, %2;" : "=f"(az), "=f"(aw) : "l"(acc2[r][1]));
            float4 o;
            o.x = ax * s + bv.x;
            o.y = ay * s + bv.y;
            o.z = az * s + bv.z;
            o.w = aw * s + bv.w;
            reinterpret_cast<float4*>(out)[(size_t)row * F4 + tcol] = o;
        }
    }
}

// ---------------------------------------------------------------------------
extern "C" void kernel_launch(void* const* d_in, const int* in_sizes, int n_in,
                              void* d_out, int out_size) {
    const float* x    = (const float*)d_in[0];
    const int*   src  = (const int*)d_in[1];
    const int*   dst  = (const int*)d_in[2];
    const float* W    = (const float*)d_in[3];
    const float* bias = (const float*)d_in[4];
    float*       out  = (float*)d_out;

    int n = in_sizes[0] / F;   // 50000
    int E = in_sizes[1];       // 800000

    k_init<<<2048, 256>>>(n);
    k_deg<<<(E + 255) / 256, 256>>>(src, dst, E);
    k_inv<<<(n + 255) / 256, 256>>>(n);
    k_scatter<<<(E + 7) / 8, 256>>>(x, src, dst, E);   // one warp per edge
    k_gemm<<<(n + 63) / 64, 256>>>(W, bias, out, n);
}